// round 15
// baseline (speedup 1.0000x reference)
#include <cuda_runtime.h>
#include <math_constants.h>

#define BB 8
#define NN 50000
#define LL 512
#define RR 5
#define GPB 256                 // blocks per batch (proven R4/R8 shape)
#define WPB 8                   // warps per block
#define WARPS_PER_BATCH (GPB * WPB)   // 2048

#define H1 200
#define H2 100
#define CC 2

// partial top/bot candidates: one sorted 5+5 set per block per batch
__device__ float g_part_top[BB * GPB * RR];   // sorted descending per 5-group
__device__ float g_part_bot[BB * GPB * RR];   // sorted ascending per 5-group

// ---------------------------------------------------------------------------
// sorted-insertion helpers
// ---------------------------------------------------------------------------
__device__ __forceinline__ void insert_max(float* arr, float v) {
    if (v > arr[RR - 1]) {
        arr[RR - 1] = v;
#pragma unroll
        for (int j = RR - 1; j > 0; j--) {
            if (arr[j] > arr[j - 1]) {
                float t = arr[j]; arr[j] = arr[j - 1]; arr[j - 1] = t;
            }
        }
    }
}
__device__ __forceinline__ void insert_min(float* arr, float v) {
    if (v < arr[RR - 1]) {
        arr[RR - 1] = v;
#pragma unroll
        for (int j = RR - 1; j > 0; j--) {
            if (arr[j] < arr[j - 1]) {
                float t = arr[j]; arr[j] = arr[j - 1]; arr[j - 1] = t;
            }
        }
    }
}

// merge two sorted-descending 5-lists -> top 5
__device__ __forceinline__ void merge_desc5(const float* a, const float* b, float* o) {
    int i = 0, j = 0;
#pragma unroll
    for (int k = 0; k < RR; k++) {
        float av = a[i], bv = b[j];
        bool ta = (av >= bv);
        o[k] = ta ? av : bv;
        i += ta; j += !ta;
    }
}
// merge two sorted-ascending 5-lists -> bottom 5
__device__ __forceinline__ void merge_asc5(const float* a, const float* b, float* o) {
    int i = 0, j = 0;
#pragma unroll
    for (int k = 0; k < RR; k++) {
        float av = a[i], bv = b[j];
        bool ta = (av <= bv);
        o[k] = ta ? av : bv;
        i += ta; j += !ta;
    }
}

// ---------------------------------------------------------------------------
// Kernel A: scores + running top-5/bot-5. grid = (GPB, BB), 256 threads.
// EXACT R4/R8 version — proven 117.5us @ 88.6% DRAM (the HBM ceiling for this
// pattern), regs=32. Do not touch.
// ---------------------------------------------------------------------------
__global__ __launch_bounds__(256) void chowder_scores_topk_kernel(
    const float* __restrict__ x,
    const float* __restrict__ conv_w,
    const float* __restrict__ conv_b)
{
    __shared__ float4 ws[LL / 4];
    __shared__ float stop[WPB * RR];
    __shared__ float sbot[WPB * RR];

    const int tid  = threadIdx.x;
    const int warp = tid >> 5;
    const int lane = tid & 31;
    const int b    = blockIdx.y;

    for (int i = tid; i < LL / 4; i += blockDim.x)
        ws[i] = reinterpret_cast<const float4*>(conv_w)[i];
    __syncthreads();

    float4 w0  = ws[0 * 32 + lane];
    float4 w1r = ws[1 * 32 + lane];
    float4 w2r = ws[2 * 32 + lane];
    float4 w3r = ws[3 * 32 + lane];

    const int gw = blockIdx.x * WPB + warp;
    const float cb = conv_b[0];
    const float* __restrict__ xb = x + (long long)b * NN * LL;

    float top[RR], bot[RR];
#pragma unroll
    for (int i = 0; i < RR; i++) { top[i] = -CUDART_INF_F; bot[i] = CUDART_INF_F; }

    for (int inst = gw; inst < NN; inst += WARPS_PER_BATCH) {
        const float4* __restrict__ xp =
            reinterpret_cast<const float4*>(xb + (long long)inst * LL);

        float4 v0 = xp[0 * 32 + lane];
        float4 v1 = xp[1 * 32 + lane];
        float4 v2 = xp[2 * 32 + lane];
        float4 v3 = xp[3 * 32 + lane];

        float acc = 0.0f;
        acc = fmaf(v0.x, w0.x,  acc); acc = fmaf(v0.y, w0.y,  acc);
        acc = fmaf(v0.z, w0.z,  acc); acc = fmaf(v0.w, w0.w,  acc);
        acc = fmaf(v1.x, w1r.x, acc); acc = fmaf(v1.y, w1r.y, acc);
        acc = fmaf(v1.z, w1r.z, acc); acc = fmaf(v1.w, w1r.w, acc);
        acc = fmaf(v2.x, w2r.x, acc); acc = fmaf(v2.y, w2r.y, acc);
        acc = fmaf(v2.z, w2r.z, acc); acc = fmaf(v2.w, w2r.w, acc);
        acc = fmaf(v3.x, w3r.x, acc); acc = fmaf(v3.y, w3r.y, acc);
        acc = fmaf(v3.z, w3r.z, acc); acc = fmaf(v3.w, w3r.w, acc);

#pragma unroll
        for (int o = 16; o; o >>= 1)
            acc += __shfl_xor_sync(0xffffffff, acc, o);

        if (lane == 0) {
            float v = acc + cb;
            insert_max(top, v);
            insert_min(bot, v);
        }
    }

    if (lane == 0) {
#pragma unroll
        for (int j = 0; j < RR; j++) {
            stop[warp * RR + j] = top[j];
            sbot[warp * RR + j] = bot[j];
        }
    }
    __syncthreads();

    if (tid == 0) {
        float ft[RR], fb[RR];
#pragma unroll
        for (int i = 0; i < RR; i++) { ft[i] = -CUDART_INF_F; fb[i] = CUDART_INF_F; }
        for (int i = 0; i < WPB * RR; i++) {
            insert_max(ft, stop[i]);
            insert_min(fb, sbot[i]);
        }
        float* pt = g_part_top + ((long long)b * GPB + blockIdx.x) * RR;
        float* pb = g_part_bot + ((long long)b * GPB + blockIdx.x) * RR;
#pragma unroll
        for (int j = 0; j < RR; j++) { pt[j] = ft[j]; pb[j] = fb[j]; }
    }
}

// ---------------------------------------------------------------------------
// Kernel B v8: PDL-overlapped merge. grid = BB, 256 threads.
//   PRE-SYNC (overlapped under kernel A, input-independent):
//     stage weights -> smem, W23 = w2@w3, W_eff/b_eff reductions
//   cudaGridDependencySynchronize()  (kernel A partials now visible)
//   POST-SYNC (critical path):
//     register-batched partials wave -> tournament -> 20-FMA matvec
// ---------------------------------------------------------------------------
__global__ __launch_bounds__(256) void chowder_merge_mlp_kernel(
    const float* __restrict__ w1, const float* __restrict__ b1,
    const float* __restrict__ w2, const float* __restrict__ b2,
    const float* __restrict__ w3, const float* __restrict__ b3,
    float* __restrict__ out)
{
    const int b   = blockIdx.x;
    const int tid = threadIdx.x;

    __shared__ float mstop[GPB * RR];       // 5 KB
    __shared__ float msbot[GPB * RR];       // 5 KB
    __shared__ float sw1[2 * RR * H1];      // 8 KB  w1 [10][200]
    __shared__ float sb1[H1];
    __shared__ float sb2[H2];
    __shared__ float sw3[H2 * CC];          // 800 B
    __shared__ float sW23[H1 * CC];         // 1.6 KB  w2@w3 [200][2]
    __shared__ float sWe[2 * RR * CC];
    __shared__ float sbe[CC];
    __shared__ float cat[2 * RR];

    // ================= PRE-SYNC: weight pipeline (overlaps kernel A) =========
    // stage w1/b1/b2/w3 (register-batched, one wave) + issue w2 row loads
    {
        float rw[8];                        // 2000 = 7*256 + 208 (predicated)
#pragma unroll
        for (int k = 0; k < 8; k++) {
            const int idx = tid + k * 256;
            rw[k] = (idx < 2 * RR * H1) ? w1[idx] : 0.0f;
        }
        float rb1  = (tid < H1)      ? b1[tid] : 0.0f;
        float rb2v = (tid < H2)      ? b2[tid] : 0.0f;
        float rw3  = (tid < H2 * CC) ? w3[tid] : 0.0f;

#pragma unroll
        for (int k = 0; k < 8; k++) {
            const int idx = tid + k * 256;
            if (idx < 2 * RR * H1) sw1[idx] = rw[k];
        }
        if (tid < H1)      sb1[tid] = rb1;
        if (tid < H2)      sb2[tid] = rb2v;
        if (tid < H2 * CC) sw3[tid] = rw3;
    }

    // w2 row loads issued before the sync (fly during the smem stores above)
    float4 vrow[H2 / 4];                    // 25 float4 (grid=8, regs free)
    if (tid < H1) {
        const float4* __restrict__ w2row =
            reinterpret_cast<const float4*>(w2 + tid * H2);
#pragma unroll
        for (int q = 0; q < H2 / 4; q++)
            vrow[q] = w2row[q];             // 25 independent LDG.128
    }
    __syncthreads();

    // W23[k][c] = sum_o w2[k][o] * w3[o][c]
    if (tid < H1) {
        float a0 = 0.0f, a1 = 0.0f;
#pragma unroll
        for (int q = 0; q < H2 / 4; q++) {
            float4 v = vrow[q];
            const int o = q * 4;
            a0 = fmaf(v.x, sw3[(o + 0) * CC + 0], a0);
            a1 = fmaf(v.x, sw3[(o + 0) * CC + 1], a1);
            a0 = fmaf(v.y, sw3[(o + 1) * CC + 0], a0);
            a1 = fmaf(v.y, sw3[(o + 1) * CC + 1], a1);
            a0 = fmaf(v.z, sw3[(o + 2) * CC + 0], a0);
            a1 = fmaf(v.z, sw3[(o + 2) * CC + 1], a1);
            a0 = fmaf(v.w, sw3[(o + 3) * CC + 0], a0);
            a1 = fmaf(v.w, sw3[(o + 3) * CC + 1], a1);
        }
        sW23[tid * CC + 0] = a0;
        sW23[tid * CC + 1] = a1;
    }
    __syncthreads();

    // W_eff: 20 outputs x 8 lanes, depth 25 + width-8 shuffle reduce
    if (tid < 160) {
        const int g = tid >> 3;
        const int r = tid & 7;
        const int i = g / CC, c = g % CC;
        float s = 0.0f;
#pragma unroll
        for (int k = r; k < H1; k += 8)
            s = fmaf(sw1[i * H1 + k], sW23[k * CC + c], s);
#pragma unroll
        for (int o2 = 4; o2; o2 >>= 1)
            s += __shfl_down_sync(0xffffffff, s, o2, 8);
        if (r == 0) sWe[g] = s;
    }
    // b_eff: 2 channels x 32 lanes, width-32 shuffle reduce
    else if (tid < 224) {
        const int c = (tid - 160) >> 5;
        const int l = (tid - 160) & 31;
        float s = 0.0f;
        for (int k = l; k < H1; k += 32)
            s = fmaf(sb1[k], sW23[k * CC + c], s);
        for (int o = l; o < H2; o += 32)
            s = fmaf(sb2[o], sw3[o * CC + c], s);
#pragma unroll
        for (int o2 = 16; o2; o2 >>= 1)
            s += __shfl_down_sync(0xffffffff, s, o2);
        if (l == 0) sbe[c] = s + b3[c];
    }

    // ================= WAIT for kernel A's partials =================
    cudaGridDependencySynchronize();
    __syncthreads();   // also orders sWe/sbe writes above

    // ================= POST-SYNC critical path =================
    // partials: register-batched (one wave)
    {
        const float* pt = g_part_top + (long long)b * GPB * RR;
        const float* pb = g_part_bot + (long long)b * GPB * RR;
        float rt[5], rb[5];                 // 1280/256 = 5 exactly
#pragma unroll
        for (int k = 0; k < 5; k++) {
            rt[k] = pt[tid + k * 256];
            rb[k] = pb[tid + k * 256];
        }
#pragma unroll
        for (int k = 0; k < 5; k++) {
            mstop[tid + k * 256] = rt[k];
            msbot[tid + k * 256] = rb[k];
        }
    }
    __syncthreads();

    // tournament: 256 sorted 5-lists -> 1, 8 levels
    for (int cnt = GPB; cnt > 1; cnt >>= 1) {
        int half = cnt >> 1;
        if (tid < half) {
            float a[RR], c[RR], o[RR];
#pragma unroll
            for (int j = 0; j < RR; j++) { a[j] = mstop[tid * RR + j]; c[j] = mstop[(tid + half) * RR + j]; }
            merge_desc5(a, c, o);
#pragma unroll
            for (int j = 0; j < RR; j++) mstop[tid * RR + j] = o[j];

#pragma unroll
            for (int j = 0; j < RR; j++) { a[j] = msbot[tid * RR + j]; c[j] = msbot[(tid + half) * RR + j]; }
            merge_asc5(a, c, o);
#pragma unroll
            for (int j = 0; j < RR; j++) msbot[tid * RR + j] = o[j];
        }
        __syncthreads();
    }
    if (tid < RR)          cat[tid] = msbot[tid];
    else if (tid < 2 * RR) cat[tid] = mstop[tid - RR];
    __syncthreads();

    // out = cat @ W_eff + b_eff
    if (tid < CC) {
        float a = sbe[tid];
#pragma unroll
        for (int i = 0; i < 2 * RR; i++)
            a = fmaf(cat[i], sWe[i * CC + tid], a);
        out[b * CC + tid] = a;
    }
}

// ---------------------------------------------------------------------------
extern "C" void kernel_launch(void* const* d_in, const int* in_sizes, int n_in,
                              void* d_out, int out_size)
{
    const float* x      = (const float*)d_in[0];
    const float* conv_w = (const float*)d_in[1];
    const float* conv_b = (const float*)d_in[2];
    const float* w1     = (const float*)d_in[3];
    const float* b1     = (const float*)d_in[4];
    const float* w2     = (const float*)d_in[5];
    const float* b2     = (const float*)d_in[6];
    const float* w3     = (const float*)d_in[7];
    const float* b3     = (const float*)d_in[8];
    float* out          = (float*)d_out;

    dim3 grid(GPB, BB);
    chowder_scores_topk_kernel<<<grid, 256>>>(x, conv_w, conv_b);

    // PDL launch: kernel B starts while A runs; its pre-sync phase
    // (weight staging + MLP collapse) overlaps A's DRAM streaming.
    cudaLaunchConfig_t cfg = {};
    cfg.gridDim  = dim3(BB, 1, 1);
    cfg.blockDim = dim3(256, 1, 1);
    cfg.dynamicSmemBytes = 0;
    cfg.stream = 0;   // legacy default stream (same as <<<>>> above)
    cudaLaunchAttribute attrs[1];
    attrs[0].id = cudaLaunchAttributeProgrammaticStreamSerialization;
    attrs[0].val.programmaticStreamSerializationAllowed = 1;
    cfg.attrs = attrs;
    cfg.numAttrs = 1;
    cudaLaunchKernelEx(&cfg, chowder_merge_mlp_kernel,
                       w1, b1, w2, b2, w3, b3, out);
}

// round 16
// speedup vs baseline: 1.0347x; 1.0347x over previous
#include <cuda_runtime.h>
#include <math_constants.h>

#define BB 8
#define NN 50000
#define LL 512
#define RR 5
#define GPB 256                 // blocks per batch (proven R4/R8 shape)
#define WPB 8                   // warps per block
#define WARPS_PER_BATCH (GPB * WPB)   // 2048

#define H1 200
#define H2 100
#define CC 2

// partial top/bot candidates: one sorted 5+5 set per block per batch
__device__ float g_part_top[BB * GPB * RR];   // sorted descending per 5-group
__device__ float g_part_bot[BB * GPB * RR];   // sorted ascending per 5-group

// ---------------------------------------------------------------------------
// sorted-insertion helpers
// ---------------------------------------------------------------------------
__device__ __forceinline__ void insert_max(float* arr, float v) {
    if (v > arr[RR - 1]) {
        arr[RR - 1] = v;
#pragma unroll
        for (int j = RR - 1; j > 0; j--) {
            if (arr[j] > arr[j - 1]) {
                float t = arr[j]; arr[j] = arr[j - 1]; arr[j - 1] = t;
            }
        }
    }
}
__device__ __forceinline__ void insert_min(float* arr, float v) {
    if (v < arr[RR - 1]) {
        arr[RR - 1] = v;
#pragma unroll
        for (int j = RR - 1; j > 0; j--) {
            if (arr[j] < arr[j - 1]) {
                float t = arr[j]; arr[j] = arr[j - 1]; arr[j - 1] = t;
            }
        }
    }
}

// merge two sorted-descending 5-lists -> top 5
__device__ __forceinline__ void merge_desc5(const float* a, const float* b, float* o) {
    int i = 0, j = 0;
#pragma unroll
    for (int k = 0; k < RR; k++) {
        float av = a[i], bv = b[j];
        bool ta = (av >= bv);
        o[k] = ta ? av : bv;
        i += ta; j += !ta;
    }
}
// merge two sorted-ascending 5-lists -> bottom 5
__device__ __forceinline__ void merge_asc5(const float* a, const float* b, float* o) {
    int i = 0, j = 0;
#pragma unroll
    for (int k = 0; k < RR; k++) {
        float av = a[i], bv = b[j];
        bool ta = (av <= bv);
        o[k] = ta ? av : bv;
        i += ta; j += !ta;
    }
}

// ---------------------------------------------------------------------------
// Kernel A: scores + running top-5/bot-5. grid = (GPB, BB), 256 threads.
// EXACT R4/R8 hot loop (proven 117.5us @ 88.6% DRAM) + PDL trigger at start.
// ---------------------------------------------------------------------------
__global__ __launch_bounds__(256) void chowder_scores_topk_kernel(
    const float* __restrict__ x,
    const float* __restrict__ conv_w,
    const float* __restrict__ conv_b)
{
    __shared__ float4 ws[LL / 4];
    __shared__ float stop[WPB * RR];
    __shared__ float sbot[WPB * RR];

    const int tid  = threadIdx.x;
    const int warp = tid >> 5;
    const int lane = tid & 31;
    const int b    = blockIdx.y;

    // PDL: arm early launch of the dependent merge kernel. Fires once all
    // blocks of this grid have executed it (i.e., when the last wave starts).
    if (tid == 0)
        cudaTriggerProgrammaticLaunchCompletion();

    for (int i = tid; i < LL / 4; i += blockDim.x)
        ws[i] = reinterpret_cast<const float4*>(conv_w)[i];
    __syncthreads();

    float4 w0  = ws[0 * 32 + lane];
    float4 w1r = ws[1 * 32 + lane];
    float4 w2r = ws[2 * 32 + lane];
    float4 w3r = ws[3 * 32 + lane];

    const int gw = blockIdx.x * WPB + warp;
    const float cb = conv_b[0];
    const float* __restrict__ xb = x + (long long)b * NN * LL;

    float top[RR], bot[RR];
#pragma unroll
    for (int i = 0; i < RR; i++) { top[i] = -CUDART_INF_F; bot[i] = CUDART_INF_F; }

    for (int inst = gw; inst < NN; inst += WARPS_PER_BATCH) {
        const float4* __restrict__ xp =
            reinterpret_cast<const float4*>(xb + (long long)inst * LL);

        float4 v0 = xp[0 * 32 + lane];
        float4 v1 = xp[1 * 32 + lane];
        float4 v2 = xp[2 * 32 + lane];
        float4 v3 = xp[3 * 32 + lane];

        float acc = 0.0f;
        acc = fmaf(v0.x, w0.x,  acc); acc = fmaf(v0.y, w0.y,  acc);
        acc = fmaf(v0.z, w0.z,  acc); acc = fmaf(v0.w, w0.w,  acc);
        acc = fmaf(v1.x, w1r.x, acc); acc = fmaf(v1.y, w1r.y, acc);
        acc = fmaf(v1.z, w1r.z, acc); acc = fmaf(v1.w, w1r.w, acc);
        acc = fmaf(v2.x, w2r.x, acc); acc = fmaf(v2.y, w2r.y, acc);
        acc = fmaf(v2.z, w2r.z, acc); acc = fmaf(v2.w, w2r.w, acc);
        acc = fmaf(v3.x, w3r.x, acc); acc = fmaf(v3.y, w3r.y, acc);
        acc = fmaf(v3.z, w3r.z, acc); acc = fmaf(v3.w, w3r.w, acc);

#pragma unroll
        for (int o = 16; o; o >>= 1)
            acc += __shfl_xor_sync(0xffffffff, acc, o);

        if (lane == 0) {
            float v = acc + cb;
            insert_max(top, v);
            insert_min(bot, v);
        }
    }

    if (lane == 0) {
#pragma unroll
        for (int j = 0; j < RR; j++) {
            stop[warp * RR + j] = top[j];
            sbot[warp * RR + j] = bot[j];
        }
    }
    __syncthreads();

    if (tid == 0) {
        float ft[RR], fb[RR];
#pragma unroll
        for (int i = 0; i < RR; i++) { ft[i] = -CUDART_INF_F; fb[i] = CUDART_INF_F; }
        for (int i = 0; i < WPB * RR; i++) {
            insert_max(ft, stop[i]);
            insert_min(fb, sbot[i]);
        }
        float* pt = g_part_top + ((long long)b * GPB + blockIdx.x) * RR;
        float* pb = g_part_bot + ((long long)b * GPB + blockIdx.x) * RR;
#pragma unroll
        for (int j = 0; j < RR; j++) { pt[j] = ft[j]; pb[j] = fb[j]; }
    }
}

// ---------------------------------------------------------------------------
// Kernel B: PDL-overlapped merge. grid = BB, 256 threads.
//   PRE-SYNC (overlapped under kernel A's tail, input-independent):
//     stage weights -> smem, W23 = w2@w3, W_eff/b_eff reductions
//   cudaGridDependencySynchronize()  (A complete -> partials visible)
//   POST-SYNC critical path:
//     register-batched partials wave -> tournament -> 20-FMA matvec
// ---------------------------------------------------------------------------
__global__ __launch_bounds__(256) void chowder_merge_mlp_kernel(
    const float* __restrict__ w1, const float* __restrict__ b1,
    const float* __restrict__ w2, const float* __restrict__ b2,
    const float* __restrict__ w3, const float* __restrict__ b3,
    float* __restrict__ out)
{
    const int b   = blockIdx.x;
    const int tid = threadIdx.x;

    __shared__ float mstop[GPB * RR];       // 5 KB
    __shared__ float msbot[GPB * RR];       // 5 KB
    __shared__ float sw1[2 * RR * H1];      // 8 KB  w1 [10][200]
    __shared__ float sb1[H1];
    __shared__ float sb2[H2];
    __shared__ float sw3[H2 * CC];          // 800 B
    __shared__ float sW23[H1 * CC];         // 1.6 KB  w2@w3 [200][2]
    __shared__ float sWe[2 * RR * CC];
    __shared__ float sbe[CC];
    __shared__ float cat[2 * RR];

    // ================= PRE-SYNC: weight pipeline (overlaps kernel A) =========
    {
        float rw[8];                        // 2000 = 7*256 + 208 (predicated)
#pragma unroll
        for (int k = 0; k < 8; k++) {
            const int idx = tid + k * 256;
            rw[k] = (idx < 2 * RR * H1) ? w1[idx] : 0.0f;
        }
        float rb1  = (tid < H1)      ? b1[tid] : 0.0f;
        float rb2v = (tid < H2)      ? b2[tid] : 0.0f;
        float rw3  = (tid < H2 * CC) ? w3[tid] : 0.0f;

#pragma unroll
        for (int k = 0; k < 8; k++) {
            const int idx = tid + k * 256;
            if (idx < 2 * RR * H1) sw1[idx] = rw[k];
        }
        if (tid < H1)      sb1[tid] = rb1;
        if (tid < H2)      sb2[tid] = rb2v;
        if (tid < H2 * CC) sw3[tid] = rw3;
    }

    // w2 row loads issued before the sync (fly during the smem stores above)
    float4 vrow[H2 / 4];                    // 25 float4 (grid=8, regs free)
    if (tid < H1) {
        const float4* __restrict__ w2row =
            reinterpret_cast<const float4*>(w2 + tid * H2);
#pragma unroll
        for (int q = 0; q < H2 / 4; q++)
            vrow[q] = w2row[q];             // 25 independent LDG.128
    }
    __syncthreads();

    // W23[k][c] = sum_o w2[k][o] * w3[o][c]
    if (tid < H1) {
        float a0 = 0.0f, a1 = 0.0f;
#pragma unroll
        for (int q = 0; q < H2 / 4; q++) {
            float4 v = vrow[q];
            const int o = q * 4;
            a0 = fmaf(v.x, sw3[(o + 0) * CC + 0], a0);
            a1 = fmaf(v.x, sw3[(o + 0) * CC + 1], a1);
            a0 = fmaf(v.y, sw3[(o + 1) * CC + 0], a0);
            a1 = fmaf(v.y, sw3[(o + 1) * CC + 1], a1);
            a0 = fmaf(v.z, sw3[(o + 2) * CC + 0], a0);
            a1 = fmaf(v.z, sw3[(o + 2) * CC + 1], a1);
            a0 = fmaf(v.w, sw3[(o + 3) * CC + 0], a0);
            a1 = fmaf(v.w, sw3[(o + 3) * CC + 1], a1);
        }
        sW23[tid * CC + 0] = a0;
        sW23[tid * CC + 1] = a1;
    }
    __syncthreads();

    // W_eff: 20 outputs x 8 lanes, depth 25 + width-8 shuffle reduce
    if (tid < 160) {
        const int g = tid >> 3;
        const int r = tid & 7;
        const int i = g / CC, c = g % CC;
        float s = 0.0f;
#pragma unroll
        for (int k = r; k < H1; k += 8)
            s = fmaf(sw1[i * H1 + k], sW23[k * CC + c], s);
#pragma unroll
        for (int o2 = 4; o2; o2 >>= 1)
            s += __shfl_down_sync(0xffffffff, s, o2, 8);
        if (r == 0) sWe[g] = s;
    }
    // b_eff: 2 channels x 32 lanes, width-32 shuffle reduce
    else if (tid < 224) {
        const int c = (tid - 160) >> 5;
        const int l = (tid - 160) & 31;
        float s = 0.0f;
        for (int k = l; k < H1; k += 32)
            s = fmaf(sb1[k], sW23[k * CC + c], s);
        for (int o = l; o < H2; o += 32)
            s = fmaf(sb2[o], sw3[o * CC + c], s);
#pragma unroll
        for (int o2 = 16; o2; o2 >>= 1)
            s += __shfl_down_sync(0xffffffff, s, o2);
        if (l == 0) sbe[c] = s + b3[c];
    }

    // ================= WAIT for kernel A completion (partials visible) ======
    cudaGridDependencySynchronize();
    __syncthreads();   // also orders sWe/sbe writes above

    // ================= POST-SYNC critical path =================
    {
        const float* pt = g_part_top + (long long)b * GPB * RR;
        const float* pb = g_part_bot + (long long)b * GPB * RR;
        float rt[5], rb[5];                 // 1280/256 = 5 exactly
#pragma unroll
        for (int k = 0; k < 5; k++) {
            rt[k] = pt[tid + k * 256];
            rb[k] = pb[tid + k * 256];
        }
#pragma unroll
        for (int k = 0; k < 5; k++) {
            mstop[tid + k * 256] = rt[k];
            msbot[tid + k * 256] = rb[k];
        }
    }
    __syncthreads();

    // tournament: 256 sorted 5-lists -> 1, 8 levels
    for (int cnt = GPB; cnt > 1; cnt >>= 1) {
        int half = cnt >> 1;
        if (tid < half) {
            float a[RR], c[RR], o[RR];
#pragma unroll
            for (int j = 0; j < RR; j++) { a[j] = mstop[tid * RR + j]; c[j] = mstop[(tid + half) * RR + j]; }
            merge_desc5(a, c, o);
#pragma unroll
            for (int j = 0; j < RR; j++) mstop[tid * RR + j] = o[j];

#pragma unroll
            for (int j = 0; j < RR; j++) { a[j] = msbot[tid * RR + j]; c[j] = msbot[(tid + half) * RR + j]; }
            merge_asc5(a, c, o);
#pragma unroll
            for (int j = 0; j < RR; j++) msbot[tid * RR + j] = o[j];
        }
        __syncthreads();
    }
    if (tid < RR)          cat[tid] = msbot[tid];
    else if (tid < 2 * RR) cat[tid] = mstop[tid - RR];
    __syncthreads();

    // out = cat @ W_eff + b_eff
    if (tid < CC) {
        float a = sbe[tid];
#pragma unroll
        for (int i = 0; i < 2 * RR; i++)
            a = fmaf(cat[i], sWe[i * CC + tid], a);
        out[b * CC + tid] = a;
    }
}

// ---------------------------------------------------------------------------
extern "C" void kernel_launch(void* const* d_in, const int* in_sizes, int n_in,
                              void* d_out, int out_size)
{
    const float* x      = (const float*)d_in[0];
    const float* conv_w = (const float*)d_in[1];
    const float* conv_b = (const float*)d_in[2];
    const float* w1     = (const float*)d_in[3];
    const float* b1     = (const float*)d_in[4];
    const float* w2     = (const float*)d_in[5];
    const float* b2     = (const float*)d_in[6];
    const float* w3     = (const float*)d_in[7];
    const float* b3     = (const float*)d_in[8];
    float* out          = (float*)d_out;

    dim3 grid(GPB, BB);
    chowder_scores_topk_kernel<<<grid, 256>>>(x, conv_w, conv_b);

    // PDL launch: kernel A's blocks execute the trigger at their start, so B
    // launches while A's last wave drains; B's pre-sync weight pipeline runs
    // under A, and only the partials->tournament->matvec tail is exposed.
    cudaLaunchConfig_t cfg = {};
    cfg.gridDim  = dim3(BB, 1, 1);
    cfg.blockDim = dim3(256, 1, 1);
    cfg.dynamicSmemBytes = 0;
    cfg.stream = 0;   // legacy default stream (same as <<<>>> above)
    cudaLaunchAttribute attrs[1];
    attrs[0].id = cudaLaunchAttributeProgrammaticStreamSerialization;
    attrs[0].val.programmaticStreamSerializationAllowed = 1;
    cfg.attrs = attrs;
    cfg.numAttrs = 1;
    cudaLaunchKernelEx(&cfg, chowder_merge_mlp_kernel,
                       w1, b1, w2, b2, w3, b3, out);
}